// round 15
// baseline (speedup 1.0000x reference)
#include <cuda_runtime.h>
#include <cuda_fp16.h>
#include <cstdint>

#define BATCH 2
#define SEQ   2048
#define EMB   1024
#define HEADS 16
#define HDIM  64
#define BH    (BATCH*HEADS)
#define ROWS  (BATCH*SEQ)

#define LOG2E 1.44269504f
#define MASK_NEG (-60000.0f)

// ---------------- scratch ----------------------------------------------------
__device__ __half g_xq[ROWS * EMB];
__device__ __half g_xk[ROWS * EMB];
__device__ __half g_xv[ROWS * EMB];
__device__ __half g_wq[EMB * EMB];
__device__ __half g_wk[EMB * EMB];
__device__ __half g_wv[EMB * EMB];
__device__ __half g_wo[EMB * EMB];
__device__ __half g_q[BH * SEQ * HDIM];    // [bh][s][d], pre-scaled log2e/8
__device__ __half g_k[BH * SEQ * HDIM];    // [bh][s][d]
__device__ __half g_v[BH * HDIM * SEQ];    // [bh][d][s]
__device__ __half g_attn[ROWS * EMB];      // [b*S+s][h*64+d]
__device__ __half g_badj[BATCH * SEQ * SEQ];  // (mask?adj*log2e:-60000), tile-permuted

// ---------------- helpers ---------------------------------------------------
__device__ __forceinline__ uint32_t pack_h2(float lo, float hi) {
    uint32_t r;
    asm("cvt.rn.f16x2.f32 %0, %1, %2;" : "=r"(r) : "f"(hi), "f"(lo));
    return r;
}
__device__ __forceinline__ float ex2(float x) {
    float y;
    asm("ex2.approx.ftz.f32 %0, %1;" : "=f"(y) : "f"(x));
    return y;
}
__device__ __forceinline__ uint32_t ex2_h2(uint32_t x) {
    uint32_t y;
    asm("ex2.approx.f16x2 %0, %1;" : "=r"(y) : "r"(x));
    return y;
}
__device__ __forceinline__ void mmaH(float* d, const uint32_t* a, uint32_t b0, uint32_t b1) {
    asm volatile(
        "mma.sync.aligned.m16n8k16.row.col.f32.f16.f16.f32 "
        "{%0,%1,%2,%3}, {%4,%5,%6,%7}, {%8,%9}, {%0,%1,%2,%3};"
        : "+f"(d[0]), "+f"(d[1]), "+f"(d[2]), "+f"(d[3])
        : "r"(a[0]), "r"(a[1]), "r"(a[2]), "r"(a[3]), "r"(b0), "r"(b1));
}
__device__ __forceinline__ void ldsm4(uint32_t* r, uint32_t addr) {
    asm volatile("ldmatrix.sync.aligned.m8n8.x4.shared.b16 {%0,%1,%2,%3}, [%4];"
                 : "=r"(r[0]), "=r"(r[1]), "=r"(r[2]), "=r"(r[3]) : "r"(addr));
}
__device__ __forceinline__ void cpa16(uint32_t dst, const void* src) {
    asm volatile("cp.async.cg.shared.global [%0], [%1], 16;" :: "r"(dst), "l"(src));
}
__device__ __forceinline__ void cp_commit() { asm volatile("cp.async.commit_group;"); }
template<int N> __device__ __forceinline__ void cp_wait() {
    asm volatile("cp.async.wait_group %0;" :: "n"(N));
}

// ---------------- merged pre-pass (cvt x7 + badj) ----------------------------
struct CvtBatch { const float4* s[7]; __half2* d[7]; int n4[7]; };
__global__ void prepass_k(CvtBatch a, const float* __restrict__ adj,
                          const int* __restrict__ mask, __half2* __restrict__ bout) {
    if (blockIdx.y < 7) {
        const float4* s = a.s[blockIdx.y];
        __half2* d = a.d[blockIdx.y];
        int n = a.n4[blockIdx.y];
        for (int i = blockIdx.x * 256 + threadIdx.x; i < n; i += gridDim.x * 256) {
            float4 v = s[i];
            d[2 * i]     = __floats2half2_rn(v.x, v.y);
            d[2 * i + 1] = __floats2half2_rn(v.z, v.w);
        }
    } else {
        const int total = BATCH * SEQ * SEQ / 2;
        for (int idx = blockIdx.x * 256 + threadIdx.x; idx < total;
             idx += gridDim.x * 256) {
            int p2 = idx & 31;
            int base = idx >> 5;
            int kt = base & 31;
            int q  = (base >> 5) & 2047;
            int b  = base >> 16;
            int jj = p2 >> 3, nt = p2 & 7;
            int k = kt * 64 + nt * 8 + 2 * jj;
            float2 v = *reinterpret_cast<const float2*>(&adj[(size_t)q * SEQ + k]);
            int2 m = *reinterpret_cast<const int2*>(&mask[((size_t)b * SEQ + q) * SEQ + k]);
            bout[idx] = __floats2half2_rn(m.x ? v.x * LOG2E : MASK_NEG,
                                          m.y ? v.y * LOG2E : MASK_NEG);
        }
    }
}

// ---------------- fp16 GEMM: 3-stage cp.async pipeline -----------------------
// smem: A stages @0,16K,32K; B stages @48K,64K,80K. 96 KB total.
#define GA_OFF 0u
#define GB_OFF 49152u
#define GEMM_SMEM 98304

struct GemmBatch {
    const __half* X[3]; const __half* W[3]; const float* bias[3];
    void* Y[3]; int layout[3]; float scale[3];
};

__global__ __launch_bounds__(256, 2) void gemm_h(GemmBatch args)
{
    extern __shared__ __align__(1024) char smem[];
    const uint32_t sb = (uint32_t)__cvta_generic_to_shared(smem);
    const int z = blockIdx.z;
    const __half* __restrict__ X = args.X[z];
    const __half* __restrict__ W = args.W[z];
    const float* __restrict__ bias = args.bias[z];
    void* Y = args.Y[z];
    const int layout = args.layout[z];
    const float scale = args.scale[z];

    const int tid = threadIdx.x, lane = tid & 31, wid = tid >> 5;
    const int g = lane >> 2, j = lane & 3;
    const int wm = (wid & 1) * 64, wn = (wid >> 1) * 32;
    const int m0 = blockIdx.y * 128, n0 = blockIdx.x * 128;

    const int c_ = tid & 7, r_ = tid >> 3;
    const uint32_t swz = (uint32_t)((c_ ^ (r_ & 7)) << 4);

    auto load_stage = [&](int c) {
        const uint32_t ab = sb + GA_OFF + (uint32_t)(c % 3) * 16384u;
        const uint32_t bb = sb + GB_OFF + (uint32_t)(c % 3) * 16384u;
        const int k0 = c * 64;
#pragma unroll
        for (int i = 0; i < 4; ++i) {
            int row = r_ + i * 32;
            cpa16(ab + (uint32_t)row * 128u + swz,
                  X + (size_t)(m0 + row) * EMB + k0 + c_ * 8);
            cpa16(bb + (uint32_t)row * 128u + swz,
                  W + (size_t)(n0 + row) * EMB + k0 + c_ * 8);
        }
    };

    float acc[4][4][4];
#pragma unroll
    for (int mt = 0; mt < 4; ++mt)
#pragma unroll
        for (int nt = 0; nt < 4; ++nt)
#pragma unroll
            for (int c = 0; c < 4; ++c) acc[mt][nt][c] = 0.f;

    const int sr  = (lane & 7) + (((lane >> 3) & 1) << 3);
    const int e   = lane >> 4;
    const int sbr = (lane & 7) + ((lane >> 4) << 3);
    const int eb  = (lane >> 3) & 1;

    load_stage(0); cp_commit();
    load_stage(1); cp_commit();
    for (int kt = 0; kt < 16; ++kt) {
        const int buf = kt % 3;
        cp_wait<1>();          // tile kt resident; kt+1 may still be in flight
        __syncthreads();       // all warps done with slot (kt+2)%3 (tile kt-1)
        if (kt + 2 < 16) load_stage(kt + 2);
        cp_commit();           // uniform group count
        const uint32_t ab = sb + GA_OFF + (uint32_t)buf * 16384u;
        const uint32_t bb = sb + GB_OFF + (uint32_t)buf * 16384u;
#pragma unroll
        for (int ks = 0; ks < 4; ++ks) {
            uint32_t afr[4][4];
#pragma unroll
            for (int mt = 0; mt < 4; ++mt) {
                int row = wm + mt * 16 + sr;
                ldsm4(afr[mt], ab + (uint32_t)row * 128u +
                               ((uint32_t)((ks * 2 + e) ^ (row & 7)) << 4));
            }
#pragma unroll
            for (int ntp = 0; ntp < 2; ++ntp) {
                int row = wn + ntp * 16 + sbr;
                uint32_t bfr[4];
                ldsm4(bfr, bb + (uint32_t)row * 128u +
                           ((uint32_t)((ks * 2 + eb) ^ (row & 7)) << 4));
#pragma unroll
                for (int mt = 0; mt < 4; ++mt) {
                    mmaH(acc[mt][2 * ntp],     afr[mt], bfr[0], bfr[1]);
                    mmaH(acc[mt][2 * ntp + 1], afr[mt], bfr[2], bfr[3]);
                }
            }
        }
    }

#pragma unroll
    for (int nt = 0; nt < 4; ++nt) {
        int n = n0 + wn + nt * 8 + 2 * j;
        float2 bb2 = *reinterpret_cast<const float2*>(&bias[n]);
#pragma unroll
        for (int mt = 0; mt < 4; ++mt) {
            int m = m0 + wm + mt * 16 + g;
            float v00 = (acc[mt][nt][0] + bb2.x) * scale;
            float v01 = (acc[mt][nt][1] + bb2.y) * scale;
            float v10 = (acc[mt][nt][2] + bb2.x) * scale;
            float v11 = (acc[mt][nt][3] + bb2.y) * scale;
            if (layout == 0) {
                float* Yf = (float*)Y;
                *reinterpret_cast<float2*>(&Yf[(size_t)m * EMB + n]) = make_float2(v00, v01);
                *reinterpret_cast<float2*>(&Yf[(size_t)(m + 8) * EMB + n]) = make_float2(v10, v11);
            } else {
                __half* Yh = (__half*)Y;
                int bI = m >> 11, s = m & 2047, h = n >> 6, d = n & 63;
                if (layout == 2) {
                    size_t base = ((size_t)(bI * HEADS + h) * SEQ + s) * HDIM + d;
                    *reinterpret_cast<__half2*>(&Yh[base]) = __floats2half2_rn(v00, v01);
                    *reinterpret_cast<__half2*>(&Yh[base + 8 * HDIM]) = __floats2half2_rn(v10, v11);
                } else {
                    size_t base = ((size_t)(bI * HEADS + h) * HDIM + d) * SEQ + s;
                    Yh[base]           = __float2half_rn(v00);
                    Yh[base + SEQ]     = __float2half_rn(v01);
                    Yh[base + 8]       = __float2half_rn(v10);
                    Yh[base + SEQ + 8] = __float2half_rn(v11);
                }
            }
        }
    }
}

// ---------------- flash attention (R14 + lacc mma batched last) --------------
#define QS_B   0u
#define STG_B  16384u
#define STG_SZ 16384u
#define ATTN_SMEM 65536
#define ONE2 0x3C003C00u   // half2(1.0, 1.0)

__global__ __launch_bounds__(256, 2) void attn_h(
    const __half* __restrict__ Qg, const __half* __restrict__ Kg,
    const __half* __restrict__ Vg, const __half* __restrict__ badj,
    __half* __restrict__ outp)
{
    extern __shared__ __align__(1024) char sm8[];
    const uint32_t sb = (uint32_t)__cvta_generic_to_shared(sm8);
    const int tid = threadIdx.x, lane = tid & 31, w = tid >> 5;
    const int g = lane >> 2, j = lane & 3;
    const int bh = blockIdx.y, b = bh >> 4, h = bh & 15;
    const int q0 = blockIdx.x * 128;

    const int c_ = tid & 7, r_ = tid >> 3;
    const uint32_t swz = (uint32_t)((c_ ^ (r_ & 7)) << 4);

    auto load_kv = [&](int t) {
        const uint32_t stb = sb + STG_B + (uint32_t)(t % 3) * STG_SZ;
        const int kn = t * 64;
#pragma unroll
        for (int i = 0; i < 2; ++i) {
            int row = r_ + i * 32;
            cpa16(stb + (uint32_t)row * 128u + swz,
                  Kg + ((size_t)bh * SEQ + kn + row) * HDIM + c_ * 8);
            cpa16(stb + 8192u + (uint32_t)row * 128u + swz,
                  Vg + ((size_t)bh * HDIM + row) * SEQ + kn + c_ * 8);
        }
    };

#pragma unroll
    for (int i = 0; i < 4; ++i) {
        int row = r_ + i * 32;
        cpa16(sb + QS_B + (uint32_t)row * 128u + swz,
              Qg + ((size_t)bh * SEQ + q0 + row) * HDIM + c_ * 8);
    }
    load_kv(0); cp_commit();
    load_kv(1); cp_commit();

    float o[8][4];
    float lacc[4] = {0.f, 0.f, 0.f, 0.f};
    float mrun0 = -1e30f, mrun1 = -1e30f;
#pragma unroll
    for (int nt = 0; nt < 8; ++nt)
#pragma unroll
        for (int c = 0; c < 4; ++c) o[nt][c] = 0.f;

    const int sr  = (lane & 7) + (((lane >> 3) & 1) << 3);
    const int e   = lane >> 4;
    const int sbr = (lane & 7) + ((lane >> 4) << 3);
    const int eb  = (lane >> 3) & 1;
    const int arow = w * 16 + sr;
    const uint32_t qab = sb + QS_B + (uint32_t)arow * 128u;

    const __half* bj0 = badj + (((size_t)b * SEQ + (q0 + w * 16 + g)) << 11) + (j << 4);
    const __half* bj1 = badj + (((size_t)b * SEQ + (q0 + w * 16 + g + 8)) << 11) + (j << 4);

    uint32_t qf[4][4];

    for (int kt = 0; kt < 32; ++kt) {
        const uint32_t stb = sb + STG_B + (uint32_t)(kt % 3) * STG_SZ;

        uint32_t pb[2][8];
#pragma unroll
        for (int r = 0; r < 2; ++r) {
            const __half* bp = (r ? bj1 : bj0) + (kt << 6);
            uint4 u0 = *reinterpret_cast<const uint4*>(bp);
            uint4 u1 = *reinterpret_cast<const uint4*>(bp + 8);
            pb[r][0] = u0.x; pb[r][1] = u0.y; pb[r][2] = u0.z; pb[r][3] = u0.w;
            pb[r][4] = u1.x; pb[r][5] = u1.y; pb[r][6] = u1.z; pb[r][7] = u1.w;
        }

        cp_wait<1>();
        __syncthreads();

        if (kt + 2 < 32) load_kv(kt + 2);
        cp_commit();

        if (kt == 0) {
#pragma unroll
            for (int ks = 0; ks < 4; ++ks)
                ldsm4(qf[ks], qab + ((uint32_t)((ks * 2 + e) ^ (arow & 7)) << 4));
        }

        float sacc[8][4];
#pragma unroll
        for (int r = 0; r < 2; ++r)
#pragma unroll
            for (int nt = 0; nt < 8; ++nt) {
                float2 ad = __half22float2(*reinterpret_cast<__half2*>(&pb[r][nt]));
                sacc[nt][r * 2]     = ad.x;
                sacc[nt][r * 2 + 1] = ad.y;
            }

#pragma unroll
        for (int ks = 0; ks < 4; ++ks) {
#pragma unroll
            for (int ntp = 0; ntp < 4; ++ntp) {
                int row = ntp * 16 + sbr;
                uint32_t bf[4];
                ldsm4(bf, stb + (uint32_t)row * 128u +
                          ((uint32_t)((ks * 2 + eb) ^ (row & 7)) << 4));
                mmaH(sacc[2 * ntp],     qf[ks], bf[0], bf[1]);
                mmaH(sacc[2 * ntp + 1], qf[ks], bf[2], bf[3]);
            }
        }

        float rowm0 = sacc[0][0], rowm1 = sacc[0][2];
#pragma unroll
        for (int nt = 0; nt < 8; ++nt) {
            rowm0 = fmaxf(rowm0, fmaxf(sacc[nt][0], sacc[nt][1]));
            rowm1 = fmaxf(rowm1, fmaxf(sacc[nt][2], sacc[nt][3]));
        }
        rowm0 = fmaxf(rowm0, __shfl_xor_sync(0xffffffffu, rowm0, 1));
        rowm1 = fmaxf(rowm1, __shfl_xor_sync(0xffffffffu, rowm1, 1));
        rowm0 = fmaxf(rowm0, __shfl_xor_sync(0xffffffffu, rowm0, 2));
        rowm1 = fmaxf(rowm1, __shfl_xor_sync(0xffffffffu, rowm1, 2));
        const float mn0 = fmaxf(rowm0, mrun0);
        const float mn1 = fmaxf(rowm1, mrun1);
        if (mn0 > mrun0) {
            float al = ex2(mrun0 - mn0);
            mrun0 = mn0;
            lacc[0] *= al; lacc[1] *= al;
#pragma unroll
            for (int nt = 0; nt < 8; ++nt) { o[nt][0] *= al; o[nt][1] *= al; }
        }
        if (mn1 > mrun1) {
            float al = ex2(mrun1 - mn1);
            mrun1 = mn1;
            lacc[2] *= al; lacc[3] *= al;
#pragma unroll
            for (int nt = 0; nt < 8; ++nt) { o[nt][2] *= al; o[nt][3] *= al; }
        }

        uint32_t pf[4][4];
#pragma unroll
        for (int nt = 0; nt < 8; ++nt) {
            pf[nt >> 1][(nt & 1) << 1] =
                ex2_h2(pack_h2(sacc[nt][0] - mn0, sacc[nt][1] - mn0));
            pf[nt >> 1][((nt & 1) << 1) | 1] =
                ex2_h2(pack_h2(sacc[nt][2] - mn1, sacc[nt][3] - mn1));
        }

        // ---- O += P V ----
        const uint32_t vb = stb + 8192u;
#pragma unroll
        for (int t = 0; t < 4; ++t) {
#pragma unroll
            for (int ntp = 0; ntp < 4; ++ntp) {
                int row = ntp * 16 + sbr;
                uint32_t bf[4];
                ldsm4(bf, vb + (uint32_t)row * 128u +
                          ((uint32_t)((t * 2 + eb) ^ (row & 7)) << 4));
                mmaH(o[2 * ntp],     pf[t], bf[0], bf[1]);
                mmaH(o[2 * ntp + 1], pf[t], bf[2], bf[3]);
            }
        }
        // ---- l += P 1 (independent batch; fills tensor pipe tail) ----
#pragma unroll
        for (int t = 0; t < 4; ++t) mmaH(lacc, pf[t], ONE2, ONE2);
    }

    const float inv0 = 1.f / lacc[0], inv1 = 1.f / lacc[2];
    const int qa = q0 + w * 16 + g;
#pragma unroll
    for (int nt = 0; nt < 8; ++nt) {
        int dcol = h * HDIM + nt * 8 + 2 * j;
        *reinterpret_cast<__half2*>(&outp[((size_t)b * SEQ + qa) * EMB + dcol]) =
            __floats2half2_rn(o[nt][0] * inv0, o[nt][1] * inv0);
        *reinterpret_cast<__half2*>(&outp[((size_t)b * SEQ + qa + 8) * EMB + dcol]) =
            __floats2half2_rn(o[nt][2] * inv1, o[nt][3] * inv1);
    }
}

// ---------------- launch -----------------------------------------------------
extern "C" void kernel_launch(void* const* d_in, const int* in_sizes, int n_in,
                              void* d_out, int out_size)
{
    const float* query = (const float*)d_in[0];
    const float* key   = (const float*)d_in[1];
    const float* value = (const float*)d_in[2];
    const float* adj   = (const float*)d_in[3];
    const int*   mask  = (const int*)d_in[4];
    const float* Wq = (const float*)d_in[5];
    const float* bq = (const float*)d_in[6];
    const float* Wk = (const float*)d_in[7];
    const float* bk = (const float*)d_in[8];
    const float* Wv = (const float*)d_in[9];
    const float* bv = (const float*)d_in[10];
    const float* Wo = (const float*)d_in[11];
    const float* bo = (const float*)d_in[12];

    __half *xq, *xk, *xv, *wq, *wk, *wv, *wo, *qq, *kk, *vv, *at, *badj;
    cudaGetSymbolAddress((void**)&xq, g_xq);
    cudaGetSymbolAddress((void**)&xk, g_xk);
    cudaGetSymbolAddress((void**)&xv, g_xv);
    cudaGetSymbolAddress((void**)&wq, g_wq);
    cudaGetSymbolAddress((void**)&wk, g_wk);
    cudaGetSymbolAddress((void**)&wv, g_wv);
    cudaGetSymbolAddress((void**)&wo, g_wo);
    cudaGetSymbolAddress((void**)&qq, g_q);
    cudaGetSymbolAddress((void**)&kk, g_k);
    cudaGetSymbolAddress((void**)&vv, g_v);
    cudaGetSymbolAddress((void**)&at, g_attn);
    cudaGetSymbolAddress((void**)&badj, g_badj);

    cudaFuncSetAttribute(attn_h, cudaFuncAttributeMaxDynamicSharedMemorySize, ATTN_SMEM);
    cudaFuncSetAttribute(gemm_h, cudaFuncAttributeMaxDynamicSharedMemorySize, GEMM_SMEM);

    CvtBatch cb;
    cb.s[0] = (const float4*)query; cb.d[0] = (__half2*)xq; cb.n4[0] = ROWS * EMB / 4;
    cb.s[1] = (const float4*)key;   cb.d[1] = (__half2*)xk; cb.n4[1] = ROWS * EMB / 4;
    cb.s[2] = (const float4*)value; cb.d[2] = (__half2*)xv; cb.n4[2] = ROWS * EMB / 4;
    cb.s[3] = (const float4*)Wq;    cb.d[3] = (__half2*)wq; cb.n4[3] = EMB * EMB / 4;
    cb.s[4] = (const float4*)Wk;    cb.d[4] = (__half2*)wk; cb.n4[4] = EMB * EMB / 4;
    cb.s[5] = (const float4*)Wv;    cb.d[5] = (__half2*)wv; cb.n4[5] = EMB * EMB / 4;
    cb.s[6] = (const float4*)Wo;    cb.d[6] = (__half2*)wo; cb.n4[6] = EMB * EMB / 4;
    prepass_k<<<dim3(1024, 8), 256>>>(cb, adj, mask, (__half2*)badj);

    GemmBatch gqkv;
    gqkv.X[0] = xq; gqkv.W[0] = wq; gqkv.bias[0] = bq; gqkv.Y[0] = qq;
    gqkv.layout[0] = 2; gqkv.scale[0] = 0.125f * LOG2E;
    gqkv.X[1] = xk; gqkv.W[1] = wk; gqkv.bias[1] = bk; gqkv.Y[1] = kk;
    gqkv.layout[1] = 2; gqkv.scale[1] = 1.0f;
    gqkv.X[2] = xv; gqkv.W[2] = wv; gqkv.bias[2] = bv; gqkv.Y[2] = vv;
    gqkv.layout[2] = 1; gqkv.scale[2] = 1.0f;
    gemm_h<<<dim3(EMB / 128, ROWS / 128, 3), 256, GEMM_SMEM>>>(gqkv);

    attn_h<<<dim3(SEQ / 128, BH), 256, ATTN_SMEM>>>(qq, kk, vv, badj, at);

    GemmBatch go;
    go.X[0] = at; go.W[0] = wo; go.bias[0] = bo; go.Y[0] = d_out;
    go.layout[0] = 0; go.scale[0] = 1.0f;
    go.X[1] = at; go.W[1] = wo; go.bias[1] = bo; go.Y[1] = d_out;
    go.layout[1] = 0; go.scale[1] = 1.0f;
    go.X[2] = at; go.W[2] = wo; go.bias[2] = bo; go.Y[2] = d_out;
    go.layout[2] = 0; go.scale[2] = 1.0f;
    gemm_h<<<dim3(EMB / 128, ROWS / 128, 1), 256, GEMM_SMEM>>>(go);
}

// round 16
// speedup vs baseline: 1.0060x; 1.0060x over previous
#include <cuda_runtime.h>
#include <cuda_fp16.h>
#include <cstdint>

#define BATCH 2
#define SEQ   2048
#define EMB   1024
#define HEADS 16
#define HDIM  64
#define BH    (BATCH*HEADS)
#define ROWS  (BATCH*SEQ)

#define LOG2E 1.44269504f
#define MASK_NEG (-60000.0f)

// ---------------- scratch ----------------------------------------------------
__device__ __half g_xq[ROWS * EMB];
__device__ __half g_xk[ROWS * EMB];
__device__ __half g_xv[ROWS * EMB];
__device__ __half g_wq[EMB * EMB];
__device__ __half g_wk[EMB * EMB];
__device__ __half g_wv[EMB * EMB];
__device__ __half g_wo[EMB * EMB];
__device__ __half g_q[BH * SEQ * HDIM];    // [bh][s][d], pre-scaled log2e/8
__device__ __half g_k[BH * SEQ * HDIM];    // [bh][s][d]
__device__ __half g_v[BH * HDIM * SEQ];    // [bh][d][s]
__device__ __half g_attn[ROWS * EMB];      // [b*S+s][h*64+d]
__device__ __half g_badj[BATCH * SEQ * SEQ];  // (mask?adj*log2e:-60000), tile-permuted

// ---------------- helpers ---------------------------------------------------
__device__ __forceinline__ uint32_t pack_h2(float lo, float hi) {
    uint32_t r;
    asm("cvt.rn.f16x2.f32 %0, %1, %2;" : "=r"(r) : "f"(hi), "f"(lo));
    return r;
}
__device__ __forceinline__ float ex2(float x) {
    float y;
    asm("ex2.approx.ftz.f32 %0, %1;" : "=f"(y) : "f"(x));
    return y;
}
__device__ __forceinline__ uint32_t ex2_h2(uint32_t x) {
    uint32_t y;
    asm("ex2.approx.f16x2 %0, %1;" : "=r"(y) : "r"(x));
    return y;
}
__device__ __forceinline__ void mmaH(float* d, const uint32_t* a, uint32_t b0, uint32_t b1) {
    asm volatile(
        "mma.sync.aligned.m16n8k16.row.col.f32.f16.f16.f32 "
        "{%0,%1,%2,%3}, {%4,%5,%6,%7}, {%8,%9}, {%0,%1,%2,%3};"
        : "+f"(d[0]), "+f"(d[1]), "+f"(d[2]), "+f"(d[3])
        : "r"(a[0]), "r"(a[1]), "r"(a[2]), "r"(a[3]), "r"(b0), "r"(b1));
}
__device__ __forceinline__ void ldsm4(uint32_t* r, uint32_t addr) {
    asm volatile("ldmatrix.sync.aligned.m8n8.x4.shared.b16 {%0,%1,%2,%3}, [%4];"
                 : "=r"(r[0]), "=r"(r[1]), "=r"(r[2]), "=r"(r[3]) : "r"(addr));
}
__device__ __forceinline__ void cpa16(uint32_t dst, const void* src) {
    asm volatile("cp.async.cg.shared.global [%0], [%1], 16;" :: "r"(dst), "l"(src));
}
__device__ __forceinline__ void cp_commit() { asm volatile("cp.async.commit_group;"); }
template<int N> __device__ __forceinline__ void cp_wait() {
    asm volatile("cp.async.wait_group %0;" :: "n"(N));
}

// ---------------- merged pre-pass (cvt x7 + badj) ----------------------------
struct CvtBatch { const float4* s[7]; __half2* d[7]; int n4[7]; };
__global__ void prepass_k(CvtBatch a, const float* __restrict__ adj,
                          const int* __restrict__ mask, __half2* __restrict__ bout) {
    if (blockIdx.y < 7) {
        const float4* s = a.s[blockIdx.y];
        __half2* d = a.d[blockIdx.y];
        int n = a.n4[blockIdx.y];
        for (int i = blockIdx.x * 256 + threadIdx.x; i < n; i += gridDim.x * 256) {
            float4 v = s[i];
            d[2 * i]     = __floats2half2_rn(v.x, v.y);
            d[2 * i + 1] = __floats2half2_rn(v.z, v.w);
        }
    } else {
        const int total = BATCH * SEQ * SEQ / 2;
        for (int idx = blockIdx.x * 256 + threadIdx.x; idx < total;
             idx += gridDim.x * 256) {
            int p2 = idx & 31;
            int base = idx >> 5;
            int kt = base & 31;
            int q  = (base >> 5) & 2047;
            int b  = base >> 16;
            int jj = p2 >> 3, nt = p2 & 7;
            int k = kt * 64 + nt * 8 + 2 * jj;
            float2 v = *reinterpret_cast<const float2*>(&adj[(size_t)q * SEQ + k]);
            int2 m = *reinterpret_cast<const int2*>(&mask[((size_t)b * SEQ + q) * SEQ + k]);
            bout[idx] = __floats2half2_rn(m.x ? v.x * LOG2E : MASK_NEG,
                                          m.y ? v.y * LOG2E : MASK_NEG);
        }
    }
}

// ---------------- fp16 GEMM TM=128 (QKV), 3-stage ----------------------------
#define GA_OFF 0u
#define GB_OFF 49152u
#define GEMM_SMEM 98304

struct GemmBatch {
    const __half* X[3]; const __half* W[3]; const float* bias[3];
    void* Y[3]; int layout[3]; float scale[3];
};

__global__ __launch_bounds__(256, 2) void gemm_h(GemmBatch args)
{
    extern __shared__ __align__(1024) char smem[];
    const uint32_t sb = (uint32_t)__cvta_generic_to_shared(smem);
    const int z = blockIdx.z;
    const __half* __restrict__ X = args.X[z];
    const __half* __restrict__ W = args.W[z];
    const float* __restrict__ bias = args.bias[z];
    void* Y = args.Y[z];
    const int layout = args.layout[z];
    const float scale = args.scale[z];

    const int tid = threadIdx.x, lane = tid & 31, wid = tid >> 5;
    const int g = lane >> 2, j = lane & 3;
    const int wm = (wid & 1) * 64, wn = (wid >> 1) * 32;
    const int m0 = blockIdx.y * 128, n0 = blockIdx.x * 128;

    const int c_ = tid & 7, r_ = tid >> 3;
    const uint32_t swz = (uint32_t)((c_ ^ (r_ & 7)) << 4);

    auto load_stage = [&](int c) {
        const uint32_t ab = sb + GA_OFF + (uint32_t)(c % 3) * 16384u;
        const uint32_t bb = sb + GB_OFF + (uint32_t)(c % 3) * 16384u;
        const int k0 = c * 64;
#pragma unroll
        for (int i = 0; i < 4; ++i) {
            int row = r_ + i * 32;
            cpa16(ab + (uint32_t)row * 128u + swz,
                  X + (size_t)(m0 + row) * EMB + k0 + c_ * 8);
            cpa16(bb + (uint32_t)row * 128u + swz,
                  W + (size_t)(n0 + row) * EMB + k0 + c_ * 8);
        }
    };

    float acc[4][4][4];
#pragma unroll
    for (int mt = 0; mt < 4; ++mt)
#pragma unroll
        for (int nt = 0; nt < 4; ++nt)
#pragma unroll
            for (int c = 0; c < 4; ++c) acc[mt][nt][c] = 0.f;

    const int sr  = (lane & 7) + (((lane >> 3) & 1) << 3);
    const int e   = lane >> 4;
    const int sbr = (lane & 7) + ((lane >> 4) << 3);
    const int eb  = (lane >> 3) & 1;

    load_stage(0); cp_commit();
    load_stage(1); cp_commit();
    for (int kt = 0; kt < 16; ++kt) {
        const int buf = kt % 3;
        cp_wait<1>();
        __syncthreads();
        if (kt + 2 < 16) load_stage(kt + 2);
        cp_commit();
        const uint32_t ab = sb + GA_OFF + (uint32_t)buf * 16384u;
        const uint32_t bb = sb + GB_OFF + (uint32_t)buf * 16384u;
#pragma unroll
        for (int ks = 0; ks < 4; ++ks) {
            uint32_t afr[4][4];
#pragma unroll
            for (int mt = 0; mt < 4; ++mt) {
                int row = wm + mt * 16 + sr;
                ldsm4(afr[mt], ab + (uint32_t)row * 128u +
                               ((uint32_t)((ks * 2 + e) ^ (row & 7)) << 4));
            }
#pragma unroll
            for (int ntp = 0; ntp < 2; ++ntp) {
                int row = wn + ntp * 16 + sbr;
                uint32_t bfr[4];
                ldsm4(bfr, bb + (uint32_t)row * 128u +
                           ((uint32_t)((ks * 2 + eb) ^ (row & 7)) << 4));
#pragma unroll
                for (int mt = 0; mt < 4; ++mt) {
                    mmaH(acc[mt][2 * ntp],     afr[mt], bfr[0], bfr[1]);
                    mmaH(acc[mt][2 * ntp + 1], afr[mt], bfr[2], bfr[3]);
                }
            }
        }
    }

#pragma unroll
    for (int nt = 0; nt < 4; ++nt) {
        int n = n0 + wn + nt * 8 + 2 * j;
        float2 bb2 = *reinterpret_cast<const float2*>(&bias[n]);
#pragma unroll
        for (int mt = 0; mt < 4; ++mt) {
            int m = m0 + wm + mt * 16 + g;
            float v00 = (acc[mt][nt][0] + bb2.x) * scale;
            float v01 = (acc[mt][nt][1] + bb2.y) * scale;
            float v10 = (acc[mt][nt][2] + bb2.x) * scale;
            float v11 = (acc[mt][nt][3] + bb2.y) * scale;
            if (layout == 0) {
                float* Yf = (float*)Y;
                *reinterpret_cast<float2*>(&Yf[(size_t)m * EMB + n]) = make_float2(v00, v01);
                *reinterpret_cast<float2*>(&Yf[(size_t)(m + 8) * EMB + n]) = make_float2(v10, v11);
            } else {
                __half* Yh = (__half*)Y;
                int bI = m >> 11, s = m & 2047, h = n >> 6, d = n & 63;
                if (layout == 2) {
                    size_t base = ((size_t)(bI * HEADS + h) * SEQ + s) * HDIM + d;
                    *reinterpret_cast<__half2*>(&Yh[base]) = __floats2half2_rn(v00, v01);
                    *reinterpret_cast<__half2*>(&Yh[base + 8 * HDIM]) = __floats2half2_rn(v10, v11);
                } else {
                    size_t base = ((size_t)(bI * HEADS + h) * HDIM + d) * SEQ + s;
                    Yh[base]           = __float2half_rn(v00);
                    Yh[base + SEQ]     = __float2half_rn(v01);
                    Yh[base + 8]       = __float2half_rn(v10);
                    Yh[base + SEQ + 8] = __float2half_rn(v11);
                }
            }
        }
    }
}

// ---------------- fp16 GEMM TM=64 (output proj), fp32 out, 3-stage -----------
// A stages 8KB @0; B stages 16KB @24576. Total 72KB.
#define G6A_OFF 0u
#define G6B_OFF 24576u
#define GEMM64_SMEM 73728

__global__ __launch_bounds__(256, 2) void gemm_h64(
    const __half* __restrict__ X, const __half* __restrict__ W,
    const float* __restrict__ bias, float* __restrict__ Y)
{
    extern __shared__ __align__(1024) char smem[];
    const uint32_t sb = (uint32_t)__cvta_generic_to_shared(smem);
    const int tid = threadIdx.x, lane = tid & 31, wid = tid >> 5;
    const int g = lane >> 2, j = lane & 3;
    const int wm = (wid & 1) * 32, wn = (wid >> 1) * 32;
    const int m0 = blockIdx.y * 64, n0 = blockIdx.x * 128;

    auto load_stage = [&](int c) {
        const uint32_t ab = sb + G6A_OFF + (uint32_t)(c % 3) * 8192u;
        const uint32_t bb = sb + G6B_OFF + (uint32_t)(c % 3) * 16384u;
        const int k0 = c * 64;
#pragma unroll
        for (int i = 0; i < 2; ++i) {  // A: 512 granules, 2/thread
            int gi = tid + i * 256;
            int row = gi >> 3, col = gi & 7;
            cpa16(ab + (uint32_t)row * 128u + ((uint32_t)((col ^ (row & 7)) << 4)),
                  X + (size_t)(m0 + row) * EMB + k0 + col * 8);
        }
#pragma unroll
        for (int i = 0; i < 4; ++i) {  // B: 1024 granules, 4/thread
            int gi = tid + i * 256;
            int row = gi >> 3, col = gi & 7;
            cpa16(bb + (uint32_t)row * 128u + ((uint32_t)((col ^ (row & 7)) << 4)),
                  W + (size_t)(n0 + row) * EMB + k0 + col * 8);
        }
    };

    float acc[2][4][4];
#pragma unroll
    for (int mt = 0; mt < 2; ++mt)
#pragma unroll
        for (int nt = 0; nt < 4; ++nt)
#pragma unroll
            for (int c = 0; c < 4; ++c) acc[mt][nt][c] = 0.f;

    const int sr  = (lane & 7) + (((lane >> 3) & 1) << 3);
    const int e   = lane >> 4;
    const int sbr = (lane & 7) + ((lane >> 4) << 3);
    const int eb  = (lane >> 3) & 1;

    load_stage(0); cp_commit();
    load_stage(1); cp_commit();
    for (int kt = 0; kt < 16; ++kt) {
        const int buf = kt % 3;
        cp_wait<1>();
        __syncthreads();
        if (kt + 2 < 16) load_stage(kt + 2);
        cp_commit();
        const uint32_t ab = sb + G6A_OFF + (uint32_t)buf * 8192u;
        const uint32_t bb = sb + G6B_OFF + (uint32_t)buf * 16384u;
#pragma unroll
        for (int ks = 0; ks < 4; ++ks) {
            uint32_t afr[2][4];
#pragma unroll
            for (int mt = 0; mt < 2; ++mt) {
                int row = wm + mt * 16 + sr;
                ldsm4(afr[mt], ab + (uint32_t)row * 128u +
                               ((uint32_t)((ks * 2 + e) ^ (row & 7)) << 4));
            }
#pragma unroll
            for (int ntp = 0; ntp < 2; ++ntp) {
                int row = wn + ntp * 16 + sbr;
                uint32_t bfr[4];
                ldsm4(bfr, bb + (uint32_t)row * 128u +
                           ((uint32_t)((ks * 2 + eb) ^ (row & 7)) << 4));
#pragma unroll
                for (int mt = 0; mt < 2; ++mt) {
                    mmaH(acc[mt][2 * ntp],     afr[mt], bfr[0], bfr[1]);
                    mmaH(acc[mt][2 * ntp + 1], afr[mt], bfr[2], bfr[3]);
                }
            }
        }
    }

#pragma unroll
    for (int nt = 0; nt < 4; ++nt) {
        int n = n0 + wn + nt * 8 + 2 * j;
        float2 bb2 = *reinterpret_cast<const float2*>(&bias[n]);
#pragma unroll
        for (int mt = 0; mt < 2; ++mt) {
            int m = m0 + wm + mt * 16 + g;
            *reinterpret_cast<float2*>(&Y[(size_t)m * EMB + n]) =
                make_float2(acc[mt][nt][0] + bb2.x, acc[mt][nt][1] + bb2.y);
            *reinterpret_cast<float2*>(&Y[(size_t)(m + 8) * EMB + n]) =
                make_float2(acc[mt][nt][2] + bb2.x, acc[mt][nt][3] + bb2.y);
        }
    }
}

// ---------------- flash attention: interleaved exp->PV per key-chunk ---------
#define QS_B   0u
#define STG_B  16384u
#define STG_SZ 16384u
#define ATTN_SMEM 65536
#define ONE2 0x3C003C00u

__global__ __launch_bounds__(256, 2) void attn_h(
    const __half* __restrict__ Qg, const __half* __restrict__ Kg,
    const __half* __restrict__ Vg, const __half* __restrict__ badj,
    __half* __restrict__ outp)
{
    extern __shared__ __align__(1024) char sm8[];
    const uint32_t sb = (uint32_t)__cvta_generic_to_shared(sm8);
    const int tid = threadIdx.x, lane = tid & 31, w = tid >> 5;
    const int g = lane >> 2, j = lane & 3;
    const int bh = blockIdx.y, b = bh >> 4, h = bh & 15;
    const int q0 = blockIdx.x * 128;

    const int c_ = tid & 7, r_ = tid >> 3;
    const uint32_t swz = (uint32_t)((c_ ^ (r_ & 7)) << 4);

    auto load_kv = [&](int t) {
        const uint32_t stb = sb + STG_B + (uint32_t)(t % 3) * STG_SZ;
        const int kn = t * 64;
#pragma unroll
        for (int i = 0; i < 2; ++i) {
            int row = r_ + i * 32;
            cpa16(stb + (uint32_t)row * 128u + swz,
                  Kg + ((size_t)bh * SEQ + kn + row) * HDIM + c_ * 8);
            cpa16(stb + 8192u + (uint32_t)row * 128u + swz,
                  Vg + ((size_t)bh * HDIM + row) * SEQ + kn + c_ * 8);
        }
    };

#pragma unroll
    for (int i = 0; i < 4; ++i) {
        int row = r_ + i * 32;
        cpa16(sb + QS_B + (uint32_t)row * 128u + swz,
              Qg + ((size_t)bh * SEQ + q0 + row) * HDIM + c_ * 8);
    }
    load_kv(0); cp_commit();
    load_kv(1); cp_commit();

    float o[8][4];
    float lacc[4] = {0.f, 0.f, 0.f, 0.f};
    float mrun0 = -1e30f, mrun1 = -1e30f;
#pragma unroll
    for (int nt = 0; nt < 8; ++nt)
#pragma unroll
        for (int c = 0; c < 4; ++c) o[nt][c] = 0.f;

    const int sr  = (lane & 7) + (((lane >> 3) & 1) << 3);
    const int e   = lane >> 4;
    const int sbr = (lane & 7) + ((lane >> 4) << 3);
    const int eb  = (lane >> 3) & 1;
    const int arow = w * 16 + sr;
    const uint32_t qab = sb + QS_B + (uint32_t)arow * 128u;

    const __half* bj0 = badj + (((size_t)b * SEQ + (q0 + w * 16 + g)) << 11) + (j << 4);
    const __half* bj1 = badj + (((size_t)b * SEQ + (q0 + w * 16 + g + 8)) << 11) + (j << 4);

    uint32_t qf[4][4];

    for (int kt = 0; kt < 32; ++kt) {
        const uint32_t stb = sb + STG_B + (uint32_t)(kt % 3) * STG_SZ;

        uint32_t pb[2][8];
#pragma unroll
        for (int r = 0; r < 2; ++r) {
            const __half* bp = (r ? bj1 : bj0) + (kt << 6);
            uint4 u0 = *reinterpret_cast<const uint4*>(bp);
            uint4 u1 = *reinterpret_cast<const uint4*>(bp + 8);
            pb[r][0] = u0.x; pb[r][1] = u0.y; pb[r][2] = u0.z; pb[r][3] = u0.w;
            pb[r][4] = u1.x; pb[r][5] = u1.y; pb[r][6] = u1.z; pb[r][7] = u1.w;
        }

        cp_wait<1>();
        __syncthreads();

        if (kt + 2 < 32) load_kv(kt + 2);
        cp_commit();

        if (kt == 0) {
#pragma unroll
            for (int ks = 0; ks < 4; ++ks)
                ldsm4(qf[ks], qab + ((uint32_t)((ks * 2 + e) ^ (arow & 7)) << 4));
        }

        float sacc[8][4];
#pragma unroll
        for (int r = 0; r < 2; ++r)
#pragma unroll
            for (int nt = 0; nt < 8; ++nt) {
                float2 ad = __half22float2(*reinterpret_cast<__half2*>(&pb[r][nt]));
                sacc[nt][r * 2]     = ad.x;
                sacc[nt][r * 2 + 1] = ad.y;
            }

#pragma unroll
        for (int ks = 0; ks < 4; ++ks) {
#pragma unroll
            for (int ntp = 0; ntp < 4; ++ntp) {
                int row = ntp * 16 + sbr;
                uint32_t bf[4];
                ldsm4(bf, stb + (uint32_t)row * 128u +
                          ((uint32_t)((ks * 2 + eb) ^ (row & 7)) << 4));
                mmaH(sacc[2 * ntp],     qf[ks], bf[0], bf[1]);
                mmaH(sacc[2 * ntp + 1], qf[ks], bf[2], bf[3]);
            }
        }

        float rowm0 = sacc[0][0], rowm1 = sacc[0][2];
#pragma unroll
        for (int nt = 0; nt < 8; ++nt) {
            rowm0 = fmaxf(rowm0, fmaxf(sacc[nt][0], sacc[nt][1]));
            rowm1 = fmaxf(rowm1, fmaxf(sacc[nt][2], sacc[nt][3]));
        }
        rowm0 = fmaxf(rowm0, __shfl_xor_sync(0xffffffffu, rowm0, 1));
        rowm1 = fmaxf(rowm1, __shfl_xor_sync(0xffffffffu, rowm1, 1));
        rowm0 = fmaxf(rowm0, __shfl_xor_sync(0xffffffffu, rowm0, 2));
        rowm1 = fmaxf(rowm1, __shfl_xor_sync(0xffffffffu, rowm1, 2));
        const float mn0 = fmaxf(rowm0, mrun0);
        const float mn1 = fmaxf(rowm1, mrun1);
        if (mn0 > mrun0) {
            float al = ex2(mrun0 - mn0);
            mrun0 = mn0;
            lacc[0] *= al; lacc[1] *= al;
#pragma unroll
            for (int nt = 0; nt < 8; ++nt) { o[nt][0] *= al; o[nt][1] *= al; }
        }
        if (mn1 > mrun1) {
            float al = ex2(mrun1 - mn1);
            mrun1 = mn1;
            lacc[2] *= al; lacc[3] *= al;
#pragma unroll
            for (int nt = 0; nt < 8; ++nt) { o[nt][2] *= al; o[nt][3] *= al; }
        }

        // ---- per key-chunk t: exp2 -> lacc mma -> PV mma (pipelined) ----
        const uint32_t vb = stb + 8192u;
#pragma unroll
        for (int t = 0; t < 4; ++t) {
            uint32_t pf[4];
            pf[0] = ex2_h2(pack_h2(sacc[2 * t][0] - mn0, sacc[2 * t][1] - mn0));
            pf[1] = ex2_h2(pack_h2(sacc[2 * t][2] - mn1, sacc[2 * t][3] - mn1));
            pf[2] = ex2_h2(pack_h2(sacc[2 * t + 1][0] - mn0, sacc[2 * t + 1][1] - mn0));
            pf[3] = ex2_h2(pack_h2(sacc[2 * t + 1][2] - mn1, sacc[2 * t + 1][3] - mn1));
            mmaH(lacc, pf, ONE2, ONE2);
#pragma unroll
            for (int ntp = 0; ntp < 4; ++ntp) {
                int row = ntp * 16 + sbr;
                uint32_t bf[4];
                ldsm4(bf, vb + (uint32_t)row * 128u +
                          ((uint32_t)((t * 2 + eb) ^ (row & 7)) << 4));
                mmaH(o[2 * ntp],     pf, bf[0], bf[1]);
                mmaH(o[2 * ntp + 1], pf, bf[2], bf[3]);
            }
        }
    }

    const float inv0 = 1.f / lacc[0], inv1 = 1.f / lacc[2];
    const int qa = q0 + w * 16 + g;
#pragma unroll
    for (int nt = 0; nt < 8; ++nt) {
        int dcol = h * HDIM + nt * 8 + 2 * j;
        *reinterpret_cast<__half2*>(&outp[((size_t)b * SEQ + qa) * EMB + dcol]) =
            __floats2half2_rn(o[nt][0] * inv0, o[nt][1] * inv0);
        *reinterpret_cast<__half2*>(&outp[((size_t)b * SEQ + qa + 8) * EMB + dcol]) =
            __floats2half2_rn(o[nt][2] * inv1, o[nt][3] * inv1);
    }
}

// ---------------- launch -----------------------------------------------------
extern "C" void kernel_launch(void* const* d_in, const int* in_sizes, int n_in,
                              void* d_out, int out_size)
{
    const float* query = (const float*)d_in[0];
    const float* key   = (const float*)d_in[1];
    const float* value = (const float*)d_in[2];
    const float* adj   = (const float*)d_in[3];
    const int*   mask  = (const int*)d_in[4];
    const float* Wq = (const float*)d_in[5];
    const float* bq = (const float*)d_in[6];
    const float* Wk = (const float*)d_in[7];
    const float* bk = (const float*)d_in[8];
    const float* Wv = (const float*)d_in[9];
    const float* bv = (const float*)d_in[10];
    const float* Wo = (const float*)d_in[11];
    const float* bo = (const float*)d_in[12];

    __half *xq, *xk, *xv, *wq, *wk, *wv, *wo, *qq, *kk, *vv, *at, *badj;
    cudaGetSymbolAddress((void**)&xq, g_xq);
    cudaGetSymbolAddress((void**)&xk, g_xk);
    cudaGetSymbolAddress((void**)&xv, g_xv);
    cudaGetSymbolAddress((void**)&wq, g_wq);
    cudaGetSymbolAddress((void**)&wk, g_wk);
    cudaGetSymbolAddress((void**)&wv, g_wv);
    cudaGetSymbolAddress((void**)&wo, g_wo);
    cudaGetSymbolAddress((void**)&qq, g_q);
    cudaGetSymbolAddress((void**)&kk, g_k);
    cudaGetSymbolAddress((void**)&vv, g_v);
    cudaGetSymbolAddress((void**)&at, g_attn);
    cudaGetSymbolAddress((void**)&badj, g_badj);

    cudaFuncSetAttribute(attn_h, cudaFuncAttributeMaxDynamicSharedMemorySize, ATTN_SMEM);
    cudaFuncSetAttribute(gemm_h, cudaFuncAttributeMaxDynamicSharedMemorySize, GEMM_SMEM);
    cudaFuncSetAttribute(gemm_h64, cudaFuncAttributeMaxDynamicSharedMemorySize, GEMM64_SMEM);

    CvtBatch cb;
    cb.s[0] = (const float4*)query; cb.d[0] = (__half2*)xq; cb.n4[0] = ROWS * EMB / 4;
    cb.s[1] = (const float4*)key;   cb.d[1] = (__half2*)xk; cb.n4[1] = ROWS * EMB / 4;
    cb.s[2] = (const float4*)value; cb.d[2] = (__half2*)xv; cb.n4[2] = ROWS * EMB / 4;
    cb.s[3] = (const float4*)Wq;    cb.d[3] = (__half2*)wq; cb.n4[3] = EMB * EMB / 4;
    cb.s[4] = (const float4*)Wk;    cb.d[4] = (__half2*)wk; cb.n4[4] = EMB * EMB / 4;
    cb.s[5] = (const float4*)Wv;    cb.d[5] = (__half2*)wv; cb.n4[5] = EMB * EMB / 4;
    cb.s[6] = (const float4*)Wo;    cb.d[6] = (__half2*)wo; cb.n4[6] = EMB * EMB / 4;
    prepass_k<<<dim3(1024, 8), 256>>>(cb, adj, mask, (__half2*)badj);

    GemmBatch gqkv;
    gqkv.X[0] = xq; gqkv.W[0] = wq; gqkv.bias[0] = bq; gqkv.Y[0] = qq;
    gqkv.layout[0] = 2; gqkv.scale[0] = 0.125f * LOG2E;
    gqkv.X[1] = xk; gqkv.W[1] = wk; gqkv.bias[1] = bk; gqkv.Y[1] = kk;
    gqkv.layout[1] = 2; gqkv.scale[1] = 1.0f;
    gqkv.X[2] = xv; gqkv.W[2] = wv; gqkv.bias[2] = bv; gqkv.Y[2] = vv;
    gqkv.layout[2] = 1; gqkv.scale[2] = 1.0f;
    gemm_h<<<dim3(EMB / 128, ROWS / 128, 3), 256, GEMM_SMEM>>>(gqkv);

    attn_h<<<dim3(SEQ / 128, BH), 256, ATTN_SMEM>>>(qq, kk, vv, badj, at);

    // output projection: TM=64 grid for wave balance (512 CTAs)
    gemm_h64<<<dim3(EMB / 128, ROWS / 64), 256, GEMM64_SMEM>>>(at, wo, bo, (float*)d_out);
}